// round 12
// baseline (speedup 1.0000x reference)
#include <cuda_runtime.h>
#include <cuda_bf16.h>
#include <cstdint>
#include <cstddef>

#define MDIM 16384
#define KDIM 4096
#define NDIM 4096
#define RDIM 16

// ---------------- scratch ----------------
__device__ __align__(128) float g_xr[(size_t)MDIM * KDIM];
__device__ __align__(128) float g_wr[(size_t)NDIM * KDIM];
__device__ __align__(128) float g_t [(size_t)MDIM * RDIM];
__device__ __align__(128) float g_bv[(size_t)NDIM * RDIM];
__device__ __align__(128) float g_bsq[NDIM];
__device__ __align__(128) float g_gram[RDIM * RDIM];
__device__ __align__(128) float g_c0[NDIM];
__device__ __align__(128) float g_W2[NDIM * RDIM];

// ---------------- helpers ----------------
__device__ __forceinline__ float rtf32(float x) {
    float r; asm("cvt.rna.tf32.f32 %0, %1;" : "=f"(r) : "f"(x)); return r;
}
__device__ __forceinline__ uint32_t s2u(const void* p) {
    uint32_t a;
    asm("{ .reg .u64 t; cvta.to.shared.u64 t, %1; cvt.u32.u64 %0, t; }" : "=r"(a) : "l"(p));
    return a;
}
#define SW128(o) ((o) ^ (((o) >> 3) & 0x70))

__device__ __forceinline__ void cp_async16(uint32_t dst, const float* src) {
    uint64_t gsrc = __cvta_generic_to_global(src);
    asm volatile("cp.async.cg.shared.global [%0], [%1], 16;" :: "r"(dst), "l"(gsrc) : "memory");
}

// tf32 mma (baseline ISA, sm_80+): D(16x8) += A(16x8,row) * B(8x8,col)
__device__ __forceinline__ void mma_tf32(float* c, const uint32_t* a, const uint32_t* b) {
    asm volatile(
        "mma.sync.aligned.m16n8k8.row.col.f32.tf32.tf32.f32 "
        "{%0,%1,%2,%3}, {%4,%5,%6,%7}, {%8,%9}, {%0,%1,%2,%3};"
        : "+f"(c[0]), "+f"(c[1]), "+f"(c[2]), "+f"(c[3])
        : "r"(a[0]), "r"(a[1]), "r"(a[2]), "r"(a[3]), "r"(b[0]), "r"(b[1]));
}

// ldmatrix x4: four 8x8-b16 (= 8x4-b32) tiles
__device__ __forceinline__ void ldsm4(uint32_t* r, uint32_t addr) {
    asm volatile("ldmatrix.sync.aligned.m8n8.x4.shared.b16 {%0,%1,%2,%3}, [%4];"
                 : "=r"(r[0]), "=r"(r[1]), "=r"(r[2]), "=r"(r[3]) : "r"(addr));
}

// ---------------- fused prep ----------------
// blocks [0,512): round x -> xr, t = x @ V^T
// blocks [512,640): round W -> wr, bv = W @ V^T, bsq
// blocks [640,896): gram[r,s] = V[r,:] . V[s,:]
__global__ __launch_bounds__(256) void k_prep(const float* __restrict__ x,
                                              const float* __restrict__ W,
                                              const float* __restrict__ V,
                                              float* __restrict__ xr,
                                              float* __restrict__ wr,
                                              float* __restrict__ t,
                                              float* __restrict__ bv,
                                              float* __restrict__ bsq,
                                              float* __restrict__ gram) {
    __shared__ float Vs[16 * 512];
    int tid = threadIdx.x, warp = tid >> 5, lane = tid & 31;
    int blk = blockIdx.x;

    if (blk >= 640) {
        // ---- gram ----
        int rs = blk - 640;
        int r = rs >> 4, s = rs & 15;
        float p = 0.f;
        for (int k = tid; k < KDIM; k += 256)
            p += V[(size_t)r * KDIM + k] * V[(size_t)s * KDIM + k];
        float* red = Vs;
        red[tid] = p;
        __syncthreads();
        for (int o = 128; o; o >>= 1) {
            if (tid < o) red[tid] += red[tid + o];
            __syncthreads();
        }
        if (tid == 0) gram[rs] = red[0];
        return;
    }

    const bool isW = (blk >= 512);
    const float* src = isW ? W : x;
    float* dst = isW ? wr : xr;
    float* tv = isW ? bv : t;
    int row0 = (isW ? (blk - 512) : blk) * 32 + warp * 4;

    float acc[4][16], accq[4];
#pragma unroll
    for (int a = 0; a < 4; a++) {
        accq[a] = 0.f;
#pragma unroll
        for (int r = 0; r < 16; r++) acc[a][r] = 0.f;
    }
    for (int ch = 0; ch < 8; ch++) {
        int kb = ch * 512;
        __syncthreads();
        for (int i = tid; i < 16 * 128; i += 256) {
            int r = i >> 7, c4 = i & 127;
            ((float4*)Vs)[r * 128 + c4] =
                ((const float4*)V)[(size_t)r * 1024 + (kb >> 2) + c4];
        }
        __syncthreads();
#pragma unroll
        for (int rr = 0; rr < 4; rr++) {
            int m = row0 + rr;
#pragma unroll
            for (int j = 0; j < 4; j++) {
                int kl = lane * 4 + j * 128;
                float4 xv = ((const float4*)src)[((size_t)m * KDIM + kb + kl) >> 2];
                float4 xq = make_float4(rtf32(xv.x), rtf32(xv.y), rtf32(xv.z), rtf32(xv.w));
                ((float4*)dst)[((size_t)m * KDIM + kb + kl) >> 2] = xq;
                if (isW)
                    accq[rr] += xv.x * xv.x + xv.y * xv.y + xv.z * xv.z + xv.w * xv.w;
#pragma unroll
                for (int r = 0; r < 16; r++) {
                    float4 vv = ((float4*)Vs)[r * 128 + (kl >> 2)];
                    acc[rr][r] += xv.x * vv.x + xv.y * vv.y + xv.z * vv.z + xv.w * vv.w;
                }
            }
        }
    }
#pragma unroll
    for (int rr = 0; rr < 4; rr++) {
        if (isW) {
            float q = accq[rr];
            for (int o = 16; o; o >>= 1) q += __shfl_xor_sync(0xFFFFFFFFu, q, o);
            if (lane == 0) bsq[row0 + rr] = q;
        }
#pragma unroll
        for (int r = 0; r < 16; r++) {
            float v = acc[rr][r];
            for (int o = 16; o; o >>= 1) v += __shfl_xor_sync(0xFFFFFFFFu, v, o);
            if (lane == 0) tv[(size_t)(row0 + rr) * 16 + r] = v;
        }
    }
}

// ---------------- prep: combine -> c0, W2 ----------------
__global__ __launch_bounds__(256) void k_comb(const float* __restrict__ U,
                                              const float* __restrict__ S,
                                              const float* __restrict__ O,
                                              const float* __restrict__ mag,
                                              const float* __restrict__ bv,
                                              const float* __restrict__ bsq,
                                              const float* __restrict__ gram,
                                              float* __restrict__ c0,
                                              float* __restrict__ W2) {
    int o = blockIdx.x * 256 + threadIdx.x;
    float Ov = O[o];
    float g[16];
#pragma unroll
    for (int r = 0; r < 16; r++) g[r] = Ov * U[(size_t)o * 16 + r] * S[r];
    float n2 = bsq[o];
#pragma unroll
    for (int r = 0; r < 16; r++) n2 += 2.f * g[r] * bv[(size_t)o * 16 + r];
#pragma unroll
    for (int r = 0; r < 16; r++) {
        float tmp = 0.f;
#pragma unroll
        for (int s = 0; s < 16; s++) tmp += g[s] * gram[r * 16 + s];
        n2 += g[r] * tmp;
    }
    float sc = mag[o] / sqrtf(n2);
    c0[o] = sc - 1.f;
#pragma unroll
    for (int r = 0; r < 16; r++) W2[(size_t)o * 16 + r] = sc * g[r];
}

// ---------------- GEMM (mma.sync tf32 + ldmatrix, 16 warps) + epilogue -----
#define BM 256
#define BN 128
#define BK 32
#define STAGES 3
#define STAGE_BYTES ((BM + BN) * BK * 4)   // A 32KB + B 16KB = 48KB
#define SMEM_TOTAL (STAGES * STAGE_BYTES)  // 144KB
#define KITERS (KDIM / BK)                 // 128

__global__ __launch_bounds__(512, 1) void k_gemm(const float* __restrict__ xr,
                                                 const float* __restrict__ wr,
                                                 const float* __restrict__ t,
                                                 const float* __restrict__ c0,
                                                 const float* __restrict__ W2,
                                                 float* __restrict__ out) {
    extern __shared__ __align__(1024) char smem[];
    const uint32_t sb = s2u(smem);
    const int tid = threadIdx.x, wid = tid >> 5, lane = tid & 31;
    const int warp_m = wid >> 2, warp_n = wid & 3;   // 4x4 warp grid, warp tile 64x32
    const int n0 = (blockIdx.x & 31) * BN;
    const int m0 = (blockIdx.x >> 5) * BM;

    float acc[4][4][4];
#pragma unroll
    for (int mt = 0; mt < 4; mt++)
#pragma unroll
        for (int nt = 0; nt < 4; nt++)
#pragma unroll
            for (int c = 0; c < 4; c++) acc[mt][nt][c] = 0.f;

    // ---- async load of one stage (512 threads) ----
    auto issue = [&](int s, int kt) {
        uint32_t sA = sb + s * STAGE_BYTES;
        uint32_t sBB = sA + BM * BK * 4;
        int k0 = kt * BK;
#pragma unroll
        for (int q = 0; q < 4; q++) {  // A: 2048 float4
            int idx = tid + q * 512;
            int row = idx >> 3, c16 = idx & 7;
            cp_async16(sA + SW128(row * 128 + c16 * 16),
                       xr + (size_t)(m0 + row) * KDIM + k0 + c16 * 4);
        }
#pragma unroll
        for (int q = 0; q < 2; q++) {  // B: 1024 float4
            int idx = tid + q * 512;
            int row = idx >> 3, c16 = idx & 7;
            cp_async16(sBB + SW128(row * 128 + c16 * 16),
                       wr + (size_t)(n0 + row) * KDIM + k0 + c16 * 4);
        }
        asm volatile("cp.async.commit_group;" ::: "memory");
    };

    issue(0, 0);
    issue(1, 1);

    // ---- ldmatrix per-lane address components ----
    const uint32_t lane7 = (uint32_t)(lane & 7);
    const uint32_t xm = lane7 << 4;
    const uint32_t selHi = (uint32_t)((lane >> 4) & 1);
    const uint32_t selLo = (uint32_t)((lane >> 3) & 1);
    uint32_t aBase[4], bBase[2];
#pragma unroll
    for (int mt = 0; mt < 4; mt++)
        aBase[mt] = (uint32_t)(warp_m * 64 + mt * 16 + selLo * 8 + lane7) * 128;
#pragma unroll
    for (int p = 0; p < 2; p++)
        bBase[p] = (uint32_t)(warp_n * 32 + p * 16 + selHi * 8 + lane7) * 128;

    for (int kt = 0; kt < KITERS; kt++) {
        asm volatile("cp.async.wait_group 1;" ::: "memory");
        __syncthreads();
        if (kt + 2 < KITERS) issue((kt + 2) % STAGES, kt + 2);

        const uint32_t sA = sb + (kt % STAGES) * STAGE_BYTES;
        const uint32_t sBB = sA + BM * BK * 4;
#pragma unroll
        for (int ks = 0; ks < 4; ks++) {
            const uint32_t aK = ((uint32_t)(ks * 32) + selHi * 16) ^ xm;
            const uint32_t bK = ((uint32_t)(ks * 32) + selLo * 16) ^ xm;
            uint32_t a[4][4];
#pragma unroll
            for (int mt = 0; mt < 4; mt++) ldsm4(a[mt], sA + aBase[mt] + aK);
            uint32_t bb[2][4];
#pragma unroll
            for (int p = 0; p < 2; p++) ldsm4(bb[p], sBB + bBase[p] + bK);
#pragma unroll
            for (int mt = 0; mt < 4; mt++)
#pragma unroll
                for (int nt = 0; nt < 4; nt++)
                    mma_tf32(acc[mt][nt], a[mt], &bb[nt >> 1][(nt & 1) * 2]);
        }
    }

    // ---- fused epilogue: out = c0[n]*acc + t[m,:] . W2[n,:] ----
    asm volatile("cp.async.wait_group 0;" ::: "memory");
    __syncthreads();
    float* W2s = (float*)smem;                    // [128][17] padded
    float* c0s = (float*)(smem + 128 * 17 * 4);   // [128]
    for (int i = tid; i < 128 * 16; i += 512) {
        int r = i >> 4, j = i & 15;
        W2s[r * 17 + j] = W2[(size_t)(n0 + r) * 16 + j];
    }
    for (int i = tid; i < 128; i += 512) c0s[i] = c0[n0 + i];
    __syncthreads();

#pragma unroll
    for (int mt = 0; mt < 4; mt++) {
        int r0 = m0 + warp_m * 64 + mt * 16 + (lane >> 2);
        float t0[16], t1[16];
#pragma unroll
        for (int j4 = 0; j4 < 4; j4++) {
            float4 v0 = ((const float4*)(t + (size_t)r0 * 16))[j4];
            float4 v1 = ((const float4*)(t + (size_t)(r0 + 8) * 16))[j4];
            t0[j4 * 4 + 0] = v0.x; t0[j4 * 4 + 1] = v0.y; t0[j4 * 4 + 2] = v0.z; t0[j4 * 4 + 3] = v0.w;
            t1[j4 * 4 + 0] = v1.x; t1[j4 * 4 + 1] = v1.y; t1[j4 * 4 + 2] = v1.z; t1[j4 * 4 + 3] = v1.w;
        }
#pragma unroll
        for (int nt = 0; nt < 4; nt++) {
            int nl = warp_n * 32 + nt * 8 + 2 * (lane & 3);
            const float* w0 = &W2s[nl * 17];
            const float* w1 = w0 + 17;
            float v00 = c0s[nl] * acc[mt][nt][0];
            float v01 = c0s[nl + 1] * acc[mt][nt][1];
            float v10 = c0s[nl] * acc[mt][nt][2];
            float v11 = c0s[nl + 1] * acc[mt][nt][3];
#pragma unroll
            for (int j = 0; j < 16; j++) {
                v00 += t0[j] * w0[j];
                v01 += t0[j] * w1[j];
                v10 += t1[j] * w0[j];
                v11 += t1[j] * w1[j];
            }
            *(float2*)(out + (size_t)r0 * NDIM + n0 + nl) = make_float2(v00, v01);
            *(float2*)(out + (size_t)(r0 + 8) * NDIM + n0 + nl) = make_float2(v10, v11);
        }
    }
}

// ---------------- launch ----------------
extern "C" void kernel_launch(void* const* d_in, const int* in_sizes, int n_in,
                              void* d_out, int out_size) {
    const float* x   = (const float*)d_in[0];
    const float* U   = (const float*)d_in[1];
    const float* V   = (const float*)d_in[2];
    const float* S   = (const float*)d_in[3];
    const float* O   = (const float*)d_in[4];
    const float* mag = (const float*)d_in[5];
    const float* W   = (const float*)d_in[6];
    float* out = (float*)d_out;

    float *xr, *wr, *t, *bv, *bsq, *gram, *c0, *W2;
    cudaGetSymbolAddress((void**)&xr, g_xr);
    cudaGetSymbolAddress((void**)&wr, g_wr);
    cudaGetSymbolAddress((void**)&t, g_t);
    cudaGetSymbolAddress((void**)&bv, g_bv);
    cudaGetSymbolAddress((void**)&bsq, g_bsq);
    cudaGetSymbolAddress((void**)&gram, g_gram);
    cudaGetSymbolAddress((void**)&c0, g_c0);
    cudaGetSymbolAddress((void**)&W2, g_W2);

    cudaFuncSetAttribute(k_gemm, cudaFuncAttributeMaxDynamicSharedMemorySize, SMEM_TOTAL);

    k_prep<<<896, 256>>>(x, W, V, xr, wr, t, bv, bsq, gram);
    k_comb<<<NDIM / 256, 256>>>(U, S, O, mag, bv, bsq, gram, c0, W2);
    k_gemm<<<(MDIM / BM) * (NDIM / BN), 512, SMEM_TOTAL>>>(xr, wr, t, c0, W2, out);
}

// round 13
// speedup vs baseline: 1.5329x; 1.5329x over previous
#include <cuda_runtime.h>
#include <cuda_bf16.h>
#include <cstdint>
#include <cstddef>

#define MDIM 16384
#define KDIM 4096
#define NDIM 4096
#define RDIM 16

// ---------------- scratch ----------------
__device__ __align__(128) float g_xr[(size_t)MDIM * KDIM];
__device__ __align__(128) float g_wr[(size_t)NDIM * KDIM];
__device__ __align__(128) float g_t [(size_t)MDIM * RDIM];
__device__ __align__(128) float g_bv[(size_t)NDIM * RDIM];
__device__ __align__(128) float g_bsq[NDIM];
__device__ __align__(128) float g_gram[RDIM * RDIM];
__device__ __align__(128) float g_c0[NDIM];
__device__ __align__(128) float g_W2[NDIM * RDIM];

// ---------------- helpers ----------------
__device__ __forceinline__ float rtf32(float x) {
    float r; asm("cvt.rna.tf32.f32 %0, %1;" : "=f"(r) : "f"(x)); return r;
}
__device__ __forceinline__ uint32_t s2u(const void* p) {
    uint32_t a;
    asm("{ .reg .u64 t; cvta.to.shared.u64 t, %1; cvt.u32.u64 %0, t; }" : "=r"(a) : "l"(p));
    return a;
}
#define SW128(o) ((o) ^ (((o) >> 3) & 0x70))

__device__ __forceinline__ void cp_async16(uint32_t dst, const float* src) {
    uint64_t gsrc = __cvta_generic_to_global(src);
    asm volatile("cp.async.cg.shared.global [%0], [%1], 16;" :: "r"(dst), "l"(gsrc) : "memory");
}

// tf32 mma (baseline ISA, sm_80+): D(16x8) += A(16x8,row) * B(8x8,col)
__device__ __forceinline__ void mma_tf32(float* c, const uint32_t* a, const uint32_t* b) {
    asm volatile(
        "mma.sync.aligned.m16n8k8.row.col.f32.tf32.tf32.f32 "
        "{%0,%1,%2,%3}, {%4,%5,%6,%7}, {%8,%9}, {%0,%1,%2,%3};"
        : "+f"(c[0]), "+f"(c[1]), "+f"(c[2]), "+f"(c[3])
        : "r"(a[0]), "r"(a[1]), "r"(a[2]), "r"(a[3]), "r"(b[0]), "r"(b[1]));
}

// ldmatrix x4: four 8x8-b16 (= 8x4-b32) tiles
__device__ __forceinline__ void ldsm4(uint32_t* r, uint32_t addr) {
    asm volatile("ldmatrix.sync.aligned.m8n8.x4.shared.b16 {%0,%1,%2,%3}, [%4];"
                 : "=r"(r[0]), "=r"(r[1]), "=r"(r[2]), "=r"(r[3]) : "r"(addr));
}

// ---------------- prep: round x -> g_xr, compute t = x @ V^T ----------------
__global__ __launch_bounds__(256) void k_xprep(const float* __restrict__ x,
                                               const float* __restrict__ V,
                                               float* __restrict__ xr,
                                               float* __restrict__ t) {
    __shared__ float Vs[16 * 512];
    int tid = threadIdx.x, warp = tid >> 5, lane = tid & 31;
    int row0 = blockIdx.x * 32 + warp * 4;
    float acc[4][16];
#pragma unroll
    for (int a = 0; a < 4; a++)
#pragma unroll
        for (int r = 0; r < 16; r++) acc[a][r] = 0.f;

    for (int ch = 0; ch < 8; ch++) {
        int kb = ch * 512;
        __syncthreads();
        for (int i = tid; i < 16 * 128; i += 256) {
            int r = i >> 7, c4 = i & 127;
            ((float4*)Vs)[r * 128 + c4] =
                ((const float4*)V)[(size_t)r * 1024 + (kb >> 2) + c4];
        }
        __syncthreads();
#pragma unroll
        for (int rr = 0; rr < 4; rr++) {
            int m = row0 + rr;
#pragma unroll
            for (int j = 0; j < 4; j++) {
                int kl = lane * 4 + j * 128;
                float4 xv = ((const float4*)x)[((size_t)m * KDIM + kb + kl) >> 2];
                float4 xq = make_float4(rtf32(xv.x), rtf32(xv.y), rtf32(xv.z), rtf32(xv.w));
                ((float4*)xr)[((size_t)m * KDIM + kb + kl) >> 2] = xq;
#pragma unroll
                for (int r = 0; r < 16; r++) {
                    float4 vv = ((float4*)Vs)[r * 128 + (kl >> 2)];
                    acc[rr][r] += xv.x * vv.x + xv.y * vv.y + xv.z * vv.z + xv.w * vv.w;
                }
            }
        }
    }
#pragma unroll
    for (int rr = 0; rr < 4; rr++)
#pragma unroll
        for (int r = 0; r < 16; r++) {
            float v = acc[rr][r];
            for (int o = 16; o; o >>= 1) v += __shfl_xor_sync(0xFFFFFFFFu, v, o);
            if (lane == 0) t[(size_t)(row0 + rr) * 16 + r] = v;
        }
}

// ---------------- prep: round W -> wr, bv = W @ V^T, bsq; blocks>=128: gram -
__global__ __launch_bounds__(256) void k_wprep(const float* __restrict__ W,
                                               const float* __restrict__ V,
                                               float* __restrict__ wr,
                                               float* __restrict__ bv,
                                               float* __restrict__ bsq,
                                               float* __restrict__ gram) {
    __shared__ float Vs[16 * 512];
    int tid = threadIdx.x, warp = tid >> 5, lane = tid & 31;

    if (blockIdx.x >= 128) {
        // ---- gram: one (r,s) pair per block ----
        int rs = blockIdx.x - 128;
        int r = rs >> 4, s = rs & 15;
        float p = 0.f;
        for (int k = tid; k < KDIM; k += 256)
            p += V[(size_t)r * KDIM + k] * V[(size_t)s * KDIM + k];
        float* red = Vs;
        red[tid] = p;
        __syncthreads();
        for (int o = 128; o; o >>= 1) {
            if (tid < o) red[tid] += red[tid + o];
            __syncthreads();
        }
        if (tid == 0) gram[rs] = red[0];
        return;
    }

    int row0 = blockIdx.x * 32 + warp * 4;
    float acc[4][16], accq[4];
#pragma unroll
    for (int a = 0; a < 4; a++) {
        accq[a] = 0.f;
#pragma unroll
        for (int r = 0; r < 16; r++) acc[a][r] = 0.f;
    }
    for (int ch = 0; ch < 8; ch++) {
        int kb = ch * 512;
        __syncthreads();
        for (int i = tid; i < 16 * 128; i += 256) {
            int r = i >> 7, c4 = i & 127;
            ((float4*)Vs)[r * 128 + c4] =
                ((const float4*)V)[(size_t)r * 1024 + (kb >> 2) + c4];
        }
        __syncthreads();
#pragma unroll
        for (int rr = 0; rr < 4; rr++) {
            int m = row0 + rr;
#pragma unroll
            for (int j = 0; j < 4; j++) {
                int kl = lane * 4 + j * 128;
                float4 xv = ((const float4*)W)[((size_t)m * KDIM + kb + kl) >> 2];
                float4 xq = make_float4(rtf32(xv.x), rtf32(xv.y), rtf32(xv.z), rtf32(xv.w));
                ((float4*)wr)[((size_t)m * KDIM + kb + kl) >> 2] = xq;
                accq[rr] += xv.x * xv.x + xv.y * xv.y + xv.z * xv.z + xv.w * xv.w;
#pragma unroll
                for (int r = 0; r < 16; r++) {
                    float4 vv = ((float4*)Vs)[r * 128 + (kl >> 2)];
                    acc[rr][r] += xv.x * vv.x + xv.y * vv.y + xv.z * vv.z + xv.w * vv.w;
                }
            }
        }
    }
#pragma unroll
    for (int rr = 0; rr < 4; rr++) {
        float q = accq[rr];
        for (int o = 16; o; o >>= 1) q += __shfl_xor_sync(0xFFFFFFFFu, q, o);
        if (lane == 0) bsq[row0 + rr] = q;
#pragma unroll
        for (int r = 0; r < 16; r++) {
            float v = acc[rr][r];
            for (int o = 16; o; o >>= 1) v += __shfl_xor_sync(0xFFFFFFFFu, v, o);
            if (lane == 0) bv[(size_t)(row0 + rr) * 16 + r] = v;
        }
    }
}

// ---------------- prep: combine -> c0, W2 ----------------
__global__ __launch_bounds__(256) void k_comb(const float* __restrict__ U,
                                              const float* __restrict__ S,
                                              const float* __restrict__ O,
                                              const float* __restrict__ mag,
                                              const float* __restrict__ bv,
                                              const float* __restrict__ bsq,
                                              const float* __restrict__ gram,
                                              float* __restrict__ c0,
                                              float* __restrict__ W2) {
    int o = blockIdx.x * 256 + threadIdx.x;
    float Ov = O[o];
    float g[16];
#pragma unroll
    for (int r = 0; r < 16; r++) g[r] = Ov * U[(size_t)o * 16 + r] * S[r];
    float n2 = bsq[o];
#pragma unroll
    for (int r = 0; r < 16; r++) n2 += 2.f * g[r] * bv[(size_t)o * 16 + r];
#pragma unroll
    for (int r = 0; r < 16; r++) {
        float tmp = 0.f;
#pragma unroll
        for (int s = 0; s < 16; s++) tmp += g[s] * gram[r * 16 + s];
        n2 += g[r] * tmp;
    }
    float sc = mag[o] / sqrtf(n2);
    c0[o] = sc - 1.f;
#pragma unroll
    for (int r = 0; r < 16; r++) W2[(size_t)o * 16 + r] = sc * g[r];
}

// ---------------- GEMM (mma.sync tf32 + ldmatrix + frag dbuf) + epilogue ---
#define BM 256
#define BN 128
#define BK 32
#define STAGES 3
#define STAGE_BYTES ((BM + BN) * BK * 4)   // A 32KB + B 16KB = 48KB
#define SMEM_TOTAL (STAGES * STAGE_BYTES)  // 144KB
#define KITERS (KDIM / BK)                 // 128

__global__ __launch_bounds__(256, 1) void k_gemm(const float* __restrict__ xr,
                                                 const float* __restrict__ wr,
                                                 const float* __restrict__ t,
                                                 const float* __restrict__ c0,
                                                 const float* __restrict__ W2,
                                                 float* __restrict__ out) {
    extern __shared__ __align__(1024) char smem[];
    const uint32_t sb = s2u(smem);
    const int tid = threadIdx.x, wid = tid >> 5, lane = tid & 31;
    const int warp_m = wid >> 1, warp_n = wid & 1;
    const int n0 = (blockIdx.x & 31) * BN;
    const int m0 = (blockIdx.x >> 5) * BM;

    float acc[4][8][4];
#pragma unroll
    for (int mt = 0; mt < 4; mt++)
#pragma unroll
        for (int nt = 0; nt < 8; nt++)
#pragma unroll
            for (int c = 0; c < 4; c++) acc[mt][nt][c] = 0.f;

    // ---- async load of one stage ----
    auto issue = [&](int s, int kt) {
        uint32_t sA = sb + s * STAGE_BYTES;
        uint32_t sBB = sA + BM * BK * 4;
        int k0 = kt * BK;
#pragma unroll
        for (int q = 0; q < 8; q++) {  // A: 2048 float4
            int idx = tid + q * 256;
            int row = idx >> 3, c16 = idx & 7;
            cp_async16(sA + SW128(row * 128 + c16 * 16),
                       xr + (size_t)(m0 + row) * KDIM + k0 + c16 * 4);
        }
#pragma unroll
        for (int q = 0; q < 4; q++) {  // B: 1024 float4
            int idx = tid + q * 256;
            int row = idx >> 3, c16 = idx & 7;
            cp_async16(sBB + SW128(row * 128 + c16 * 16),
                       wr + (size_t)(n0 + row) * KDIM + k0 + c16 * 4);
        }
        asm volatile("cp.async.commit_group;" ::: "memory");
    };

    issue(0, 0);
    issue(1, 1);

    // ---- ldmatrix per-lane address components ----
    const uint32_t lane7 = (uint32_t)(lane & 7);
    const uint32_t xm = lane7 << 4;
    const uint32_t selHi = (uint32_t)((lane >> 4) & 1);
    const uint32_t selLo = (uint32_t)((lane >> 3) & 1);
    uint32_t aBase[4], bBase[4];
#pragma unroll
    for (int mt = 0; mt < 4; mt++)
        aBase[mt] = (uint32_t)(warp_m * 64 + mt * 16 + selLo * 8 + lane7) * 128;
#pragma unroll
    for (int p = 0; p < 4; p++)
        bBase[p] = (uint32_t)(warp_n * 64 + p * 16 + selHi * 8 + lane7) * 128;

    // fragment double buffers
    uint32_t a[2][4][4], bb[2][4][4];

    for (int kt = 0; kt < KITERS; kt++) {
        asm volatile("cp.async.wait_group 1;" ::: "memory");
        __syncthreads();
        if (kt + 2 < KITERS) issue((kt + 2) % STAGES, kt + 2);

        const uint32_t sA = sb + (kt % STAGES) * STAGE_BYTES;
        const uint32_t sBB = sA + BM * BK * 4;

        // prime ks=0 fragments
        {
            const uint32_t aK = (selHi * 16) ^ xm;
            const uint32_t bK = (selLo * 16) ^ xm;
#pragma unroll
            for (int mt = 0; mt < 4; mt++) ldsm4(a[0][mt], sA + aBase[mt] + aK);
#pragma unroll
            for (int p = 0; p < 4; p++) ldsm4(bb[0][p], sBB + bBase[p] + bK);
        }
#pragma unroll
        for (int ks = 0; ks < 4; ks++) {
            const int cur = ks & 1, nxt = cur ^ 1;
            if (ks < 3) {  // prefetch ks+1 fragments while current mma issues
                const uint32_t aK = ((uint32_t)((ks + 1) * 32) + selHi * 16) ^ xm;
                const uint32_t bK = ((uint32_t)((ks + 1) * 32) + selLo * 16) ^ xm;
#pragma unroll
                for (int mt = 0; mt < 4; mt++) ldsm4(a[nxt][mt], sA + aBase[mt] + aK);
#pragma unroll
                for (int p = 0; p < 4; p++) ldsm4(bb[nxt][p], sBB + bBase[p] + bK);
            }
#pragma unroll
            for (int mt = 0; mt < 4; mt++)
#pragma unroll
                for (int nt = 0; nt < 8; nt++)
                    mma_tf32(acc[mt][nt], a[cur][mt], &bb[cur][nt >> 1][(nt & 1) * 2]);
        }
    }

    // ---- fused epilogue: out = c0[n]*acc + t[m,:] . W2[n,:] ----
    asm volatile("cp.async.wait_group 0;" ::: "memory");
    __syncthreads();
    float* W2s = (float*)smem;                    // [128][17] padded
    float* c0s = (float*)(smem + 128 * 17 * 4);   // [128]
    for (int i = tid; i < 128 * 16; i += 256) {
        int r = i >> 4, j = i & 15;
        W2s[r * 17 + j] = W2[(size_t)(n0 + r) * 16 + j];
    }
    for (int i = tid; i < 128; i += 256) c0s[i] = c0[n0 + i];
    __syncthreads();

#pragma unroll
    for (int mt = 0; mt < 4; mt++) {
        int r0 = m0 + warp_m * 64 + mt * 16 + (lane >> 2);
        float t0[16], t1[16];
#pragma unroll
        for (int j4 = 0; j4 < 4; j4++) {
            float4 v0 = ((const float4*)(t + (size_t)r0 * 16))[j4];
            float4 v1 = ((const float4*)(t + (size_t)(r0 + 8) * 16))[j4];
            t0[j4 * 4 + 0] = v0.x; t0[j4 * 4 + 1] = v0.y; t0[j4 * 4 + 2] = v0.z; t0[j4 * 4 + 3] = v0.w;
            t1[j4 * 4 + 0] = v1.x; t1[j4 * 4 + 1] = v1.y; t1[j4 * 4 + 2] = v1.z; t1[j4 * 4 + 3] = v1.w;
        }
#pragma unroll
        for (int nt = 0; nt < 8; nt++) {
            int nl = warp_n * 64 + nt * 8 + 2 * (lane & 3);
            const float* w0 = &W2s[nl * 17];
            const float* w1 = w0 + 17;
            float v00 = c0s[nl] * acc[mt][nt][0];
            float v01 = c0s[nl + 1] * acc[mt][nt][1];
            float v10 = c0s[nl] * acc[mt][nt][2];
            float v11 = c0s[nl + 1] * acc[mt][nt][3];
#pragma unroll
            for (int j = 0; j < 16; j++) {
                v00 += t0[j] * w0[j];
                v01 += t0[j] * w1[j];
                v10 += t1[j] * w0[j];
                v11 += t1[j] * w1[j];
            }
            *(float2*)(out + (size_t)r0 * NDIM + n0 + nl) = make_float2(v00, v01);
            *(float2*)(out + (size_t)(r0 + 8) * NDIM + n0 + nl) = make_float2(v10, v11);
        }
    }
}

// ---------------- launch ----------------
extern "C" void kernel_launch(void* const* d_in, const int* in_sizes, int n_in,
                              void* d_out, int out_size) {
    const float* x   = (const float*)d_in[0];
    const float* U   = (const float*)d_in[1];
    const float* V   = (const float*)d_in[2];
    const float* S   = (const float*)d_in[3];
    const float* O   = (const float*)d_in[4];
    const float* mag = (const float*)d_in[5];
    const float* W   = (const float*)d_in[6];
    float* out = (float*)d_out;

    float *xr, *wr, *t, *bv, *bsq, *gram, *c0, *W2;
    cudaGetSymbolAddress((void**)&xr, g_xr);
    cudaGetSymbolAddress((void**)&wr, g_wr);
    cudaGetSymbolAddress((void**)&t, g_t);
    cudaGetSymbolAddress((void**)&bv, g_bv);
    cudaGetSymbolAddress((void**)&bsq, g_bsq);
    cudaGetSymbolAddress((void**)&gram, g_gram);
    cudaGetSymbolAddress((void**)&c0, g_c0);
    cudaGetSymbolAddress((void**)&W2, g_W2);

    cudaFuncSetAttribute(k_gemm, cudaFuncAttributeMaxDynamicSharedMemorySize, SMEM_TOTAL);

    k_xprep<<<MDIM / 32, 256>>>(x, V, xr, t);
    k_wprep<<<128 + 256, 256>>>(W, V, wr, bv, bsq, gram);
    k_comb<<<NDIM / 256, 256>>>(U, S, O, mag, bv, bsq, gram, c0, W2);
    k_gemm<<<(MDIM / BM) * (NDIM / BN), 256, SMEM_TOTAL>>>(xr, wr, t, c0, W2, out);
}

// round 15
// speedup vs baseline: 1.7424x; 1.1367x over previous
#include <cuda_runtime.h>
#include <cuda_bf16.h>
#include <cstdint>
#include <cstddef>

#define MDIM 16384
#define KDIM 4096
#define NDIM 4096
#define RDIM 16

// ---------------- scratch ----------------
__device__ __align__(128) float g_xr[(size_t)MDIM * KDIM];
__device__ __align__(128) float g_wr[(size_t)NDIM * KDIM];
__device__ __align__(128) float g_t [(size_t)MDIM * RDIM];
__device__ __align__(128) float g_bv[(size_t)NDIM * RDIM];
__device__ __align__(128) float g_bsq[NDIM];
__device__ __align__(128) float g_gram[RDIM * RDIM];
__device__ __align__(128) float g_c0[NDIM];
__device__ __align__(128) float g_W2[NDIM * RDIM];

// ---------------- helpers ----------------
__device__ __forceinline__ float rtf32(float x) {
    float r; asm("cvt.rna.tf32.f32 %0, %1;" : "=f"(r) : "f"(x)); return r;
}
__device__ __forceinline__ uint32_t s2u(const void* p) {
    uint32_t a;
    asm("{ .reg .u64 t; cvta.to.shared.u64 t, %1; cvt.u32.u64 %0, t; }" : "=r"(a) : "l"(p));
    return a;
}
#define SW128(o) ((o) ^ (((o) >> 3) & 0x70))

__device__ __forceinline__ void cp_async16(uint32_t dst, const float* src) {
    uint64_t gsrc = __cvta_generic_to_global(src);
    asm volatile("cp.async.cg.shared.global [%0], [%1], 16;" :: "r"(dst), "l"(gsrc) : "memory");
}

// tf32 mma (baseline ISA, sm_80+): D(16x8) += A(16x8,row) * B(8x8,col)
__device__ __forceinline__ void mma_tf32(float* c, const uint32_t* a, const uint32_t* b) {
    asm volatile(
        "mma.sync.aligned.m16n8k8.row.col.f32.tf32.tf32.f32 "
        "{%0,%1,%2,%3}, {%4,%5,%6,%7}, {%8,%9}, {%0,%1,%2,%3};"
        : "+f"(c[0]), "+f"(c[1]), "+f"(c[2]), "+f"(c[3])
        : "r"(a[0]), "r"(a[1]), "r"(a[2]), "r"(a[3]), "r"(b[0]), "r"(b[1]));
}

// ldmatrix x4: four 8x8-b16 (= 8x4-b32) tiles
__device__ __forceinline__ void ldsm4(uint32_t* r, uint32_t addr) {
    asm volatile("ldmatrix.sync.aligned.m8n8.x4.shared.b16 {%0,%1,%2,%3}, [%4];"
                 : "=r"(r[0]), "=r"(r[1]), "=r"(r[2]), "=r"(r[3]) : "r"(addr));
}

// ---------------- prep: round x -> g_xr, compute t = x @ V^T ----------------
__global__ __launch_bounds__(256) void k_xprep(const float* __restrict__ x,
                                               const float* __restrict__ V,
                                               float* __restrict__ xr,
                                               float* __restrict__ t) {
    __shared__ float Vs[16 * 512];
    int tid = threadIdx.x, warp = tid >> 5, lane = tid & 31;
    int row0 = blockIdx.x * 32 + warp * 4;
    float acc[4][16];
#pragma unroll
    for (int a = 0; a < 4; a++)
#pragma unroll
        for (int r = 0; r < 16; r++) acc[a][r] = 0.f;

    for (int ch = 0; ch < 8; ch++) {
        int kb = ch * 512;
        __syncthreads();
        for (int i = tid; i < 16 * 128; i += 256) {
            int r = i >> 7, c4 = i & 127;
            ((float4*)Vs)[r * 128 + c4] =
                ((const float4*)V)[(size_t)r * 1024 + (kb >> 2) + c4];
        }
        __syncthreads();
#pragma unroll
        for (int rr = 0; rr < 4; rr++) {
            int m = row0 + rr;
#pragma unroll
            for (int j = 0; j < 4; j++) {
                int kl = lane * 4 + j * 128;
                float4 xv = ((const float4*)x)[((size_t)m * KDIM + kb + kl) >> 2];
                float4 xq = make_float4(rtf32(xv.x), rtf32(xv.y), rtf32(xv.z), rtf32(xv.w));
                ((float4*)xr)[((size_t)m * KDIM + kb + kl) >> 2] = xq;
#pragma unroll
                for (int r = 0; r < 16; r++) {
                    float4 vv = ((float4*)Vs)[r * 128 + (kl >> 2)];
                    acc[rr][r] += xv.x * vv.x + xv.y * vv.y + xv.z * vv.z + xv.w * vv.w;
                }
            }
        }
    }
#pragma unroll
    for (int rr = 0; rr < 4; rr++)
#pragma unroll
        for (int r = 0; r < 16; r++) {
            float v = acc[rr][r];
            for (int o = 16; o; o >>= 1) v += __shfl_xor_sync(0xFFFFFFFFu, v, o);
            if (lane == 0) t[(size_t)(row0 + rr) * 16 + r] = v;
        }
}

// ---------------- prep: round W -> wr, bv = W @ V^T, bsq; blocks>=128: gram -
__global__ __launch_bounds__(256) void k_wprep(const float* __restrict__ W,
                                               const float* __restrict__ V,
                                               float* __restrict__ wr,
                                               float* __restrict__ bv,
                                               float* __restrict__ bsq,
                                               float* __restrict__ gram) {
    __shared__ float Vs[16 * 512];
    int tid = threadIdx.x, warp = tid >> 5, lane = tid & 31;

    if (blockIdx.x >= 128) {
        // ---- gram: one (r,s) pair per block ----
        int rs = blockIdx.x - 128;
        int r = rs >> 4, s = rs & 15;
        float p = 0.f;
        for (int k = tid; k < KDIM; k += 256)
            p += V[(size_t)r * KDIM + k] * V[(size_t)s * KDIM + k];
        float* red = Vs;
        red[tid] = p;
        __syncthreads();
        for (int o = 128; o; o >>= 1) {
            if (tid < o) red[tid] += red[tid + o];
            __syncthreads();
        }
        if (tid == 0) gram[rs] = red[0];
        return;
    }

    int row0 = blockIdx.x * 32 + warp * 4;
    float acc[4][16], accq[4];
#pragma unroll
    for (int a = 0; a < 4; a++) {
        accq[a] = 0.f;
#pragma unroll
        for (int r = 0; r < 16; r++) acc[a][r] = 0.f;
    }
    for (int ch = 0; ch < 8; ch++) {
        int kb = ch * 512;
        __syncthreads();
        for (int i = tid; i < 16 * 128; i += 256) {
            int r = i >> 7, c4 = i & 127;
            ((float4*)Vs)[r * 128 + c4] =
                ((const float4*)V)[(size_t)r * 1024 + (kb >> 2) + c4];
        }
        __syncthreads();
#pragma unroll
        for (int rr = 0; rr < 4; rr++) {
            int m = row0 + rr;
#pragma unroll
            for (int j = 0; j < 4; j++) {
                int kl = lane * 4 + j * 128;
                float4 xv = ((const float4*)W)[((size_t)m * KDIM + kb + kl) >> 2];
                float4 xq = make_float4(rtf32(xv.x), rtf32(xv.y), rtf32(xv.z), rtf32(xv.w));
                ((float4*)wr)[((size_t)m * KDIM + kb + kl) >> 2] = xq;
                accq[rr] += xv.x * xv.x + xv.y * xv.y + xv.z * xv.z + xv.w * xv.w;
#pragma unroll
                for (int r = 0; r < 16; r++) {
                    float4 vv = ((float4*)Vs)[r * 128 + (kl >> 2)];
                    acc[rr][r] += xv.x * vv.x + xv.y * vv.y + xv.z * vv.z + xv.w * vv.w;
                }
            }
        }
    }
#pragma unroll
    for (int rr = 0; rr < 4; rr++) {
        float q = accq[rr];
        for (int o = 16; o; o >>= 1) q += __shfl_xor_sync(0xFFFFFFFFu, q, o);
        if (lane == 0) bsq[row0 + rr] = q;
#pragma unroll
        for (int r = 0; r < 16; r++) {
            float v = acc[rr][r];
            for (int o = 16; o; o >>= 1) v += __shfl_xor_sync(0xFFFFFFFFu, v, o);
            if (lane == 0) bv[(size_t)(row0 + rr) * 16 + r] = v;
        }
    }
}

// ---------------- prep: combine -> c0, W2 ----------------
__global__ __launch_bounds__(256) void k_comb(const float* __restrict__ U,
                                              const float* __restrict__ S,
                                              const float* __restrict__ O,
                                              const float* __restrict__ mag,
                                              const float* __restrict__ bv,
                                              const float* __restrict__ bsq,
                                              const float* __restrict__ gram,
                                              float* __restrict__ c0,
                                              float* __restrict__ W2) {
    int o = blockIdx.x * 256 + threadIdx.x;
    float Ov = O[o];
    float g[16];
#pragma unroll
    for (int r = 0; r < 16; r++) g[r] = Ov * U[(size_t)o * 16 + r] * S[r];
    float n2 = bsq[o];
#pragma unroll
    for (int r = 0; r < 16; r++) n2 += 2.f * g[r] * bv[(size_t)o * 16 + r];
#pragma unroll
    for (int r = 0; r < 16; r++) {
        float tmp = 0.f;
#pragma unroll
        for (int s = 0; s < 16; s++) tmp += g[s] * gram[r * 16 + s];
        n2 += g[r] * tmp;
    }
    float sc = mag[o] / sqrtf(n2);
    c0[o] = sc - 1.f;
#pragma unroll
    for (int r = 0; r < 16; r++) W2[(size_t)o * 16 + r] = sc * g[r];
}

// ---------------- GEMM (tf32 mma, 2 CTAs/SM) + fused epilogue --------------
#define BM 128
#define BN 128
#define BK 32
#define STAGES 3
#define STAGE_BYTES ((BM + BN) * BK * 4)   // A 16KB + B 16KB = 32KB
#define SMEM_TOTAL (STAGES * STAGE_BYTES)  // 96KB -> 2 CTAs/SM
#define KITERS (KDIM / BK)                 // 128

__global__ __launch_bounds__(256, 2) void k_gemm(const float* __restrict__ xr,
                                                 const float* __restrict__ wr,
                                                 const float* __restrict__ t,
                                                 const float* __restrict__ c0,
                                                 const float* __restrict__ W2,
                                                 float* __restrict__ out) {
    extern __shared__ __align__(1024) char smem[];
    const uint32_t sb = s2u(smem);
    const int tid = threadIdx.x, wid = tid >> 5, lane = tid & 31;
    const int warp_m = wid >> 2, warp_n = wid & 3;   // 2x4 warp grid, warp tile 64x32
    const int n0 = (blockIdx.x & 31) * BN;
    const int m0 = (blockIdx.x >> 5) * BM;

    float acc[4][4][4];
#pragma unroll
    for (int mt = 0; mt < 4; mt++)
#pragma unroll
        for (int nt = 0; nt < 4; nt++)
#pragma unroll
            for (int c = 0; c < 4; c++) acc[mt][nt][c] = 0.f;

    // ---- async load of one stage (256 threads, 8 float4 each) ----
    auto issue = [&](int s, int kt) {
        uint32_t sA = sb + s * STAGE_BYTES;
        uint32_t sBB = sA + BM * BK * 4;
        int k0 = kt * BK;
#pragma unroll
        for (int q = 0; q < 4; q++) {  // A: 1024 float4
            int idx = tid + q * 256;
            int row = idx >> 3, c16 = idx & 7;
            cp_async16(sA + SW128(row * 128 + c16 * 16),
                       xr + (size_t)(m0 + row) * KDIM + k0 + c16 * 4);
        }
#pragma unroll
        for (int q = 0; q < 4; q++) {  // B: 1024 float4
            int idx = tid + q * 256;
            int row = idx >> 3, c16 = idx & 7;
            cp_async16(sBB + SW128(row * 128 + c16 * 16),
                       wr + (size_t)(n0 + row) * KDIM + k0 + c16 * 4);
        }
        asm volatile("cp.async.commit_group;" ::: "memory");
    };

    issue(0, 0);
    issue(1, 1);

    // ---- ldmatrix per-lane address components ----
    const uint32_t lane7 = (uint32_t)(lane & 7);
    const uint32_t xm = lane7 << 4;
    const uint32_t selHi = (uint32_t)((lane >> 4) & 1);
    const uint32_t selLo = (uint32_t)((lane >> 3) & 1);
    uint32_t aBase[4], bBase[2];
#pragma unroll
    for (int mt = 0; mt < 4; mt++)
        aBase[mt] = (uint32_t)(warp_m * 64 + mt * 16 + selLo * 8 + lane7) * 128;
#pragma unroll
    for (int p = 0; p < 2; p++)
        bBase[p] = (uint32_t)(warp_n * 32 + p * 16 + selHi * 8 + lane7) * 128;

    for (int kt = 0; kt < KITERS; kt++) {
        asm volatile("cp.async.wait_group 1;" ::: "memory");
        __syncthreads();
        if (kt + 2 < KITERS) issue((kt + 2) % STAGES, kt + 2);

        const uint32_t sA = sb + (kt % STAGES) * STAGE_BYTES;
        const uint32_t sBB = sA + BM * BK * 4;
#pragma unroll
        for (int ks = 0; ks < 4; ks++) {
            const uint32_t aK = ((uint32_t)(ks * 32) + selHi * 16) ^ xm;
            const uint32_t bK = ((uint32_t)(ks * 32) + selLo * 16) ^ xm;
            uint32_t a[4][4];
#pragma unroll
            for (int mt = 0; mt < 4; mt++) ldsm4(a[mt], sA + aBase[mt] + aK);
            uint32_t bb[2][4];
#pragma unroll
            for (int p = 0; p < 2; p++) ldsm4(bb[p], sBB + bBase[p] + bK);
#pragma unroll
            for (int mt = 0; mt < 4; mt++)
#pragma unroll
                for (int nt = 0; nt < 4; nt++)
                    mma_tf32(acc[mt][nt], a[mt], &bb[nt >> 1][(nt & 1) * 2]);
        }
    }

    // ---- fused epilogue: out = c0[n]*acc + t[m,:] . W2[n,:] ----
    asm volatile("cp.async.wait_group 0;" ::: "memory");
    __syncthreads();
    float* W2s = (float*)smem;                    // [128][17] padded
    float* c0s = (float*)(smem + 128 * 17 * 4);   // [128]
    for (int i = tid; i < 128 * 16; i += 256) {
        int r = i >> 4, j = i & 15;
        W2s[r * 17 + j] = W2[(size_t)(n0 + r) * 16 + j];
    }
    for (int i = tid; i < 128; i += 256) c0s[i] = c0[n0 + i];
    __syncthreads();

#pragma unroll
    for (int mt = 0; mt < 4; mt++) {
        int r0 = m0 + warp_m * 64 + mt * 16 + (lane >> 2);
        float t0[16], t1[16];
#pragma unroll
        for (int j4 = 0; j4 < 4; j4++) {
            float4 v0 = ((const float4*)(t + (size_t)r0 * 16))[j4];
            float4 v1 = ((const float4*)(t + (size_t)(r0 + 8) * 16))[j4];
            t0[j4 * 4 + 0] = v0.x; t0[j4 * 4 + 1] = v0.y; t0[j4 * 4 + 2] = v0.z; t0[j4 * 4 + 3] = v0.w;
            t1[j4 * 4 + 0] = v1.x; t1[j4 * 4 + 1] = v1.y; t1[j4 * 4 + 2] = v1.z; t1[j4 * 4 + 3] = v1.w;
        }
#pragma unroll
        for (int nt = 0; nt < 4; nt++) {
            int nl = warp_n * 32 + nt * 8 + 2 * (lane & 3);
            const float* w0 = &W2s[nl * 17];
            const float* w1 = w0 + 17;
            float v00 = c0s[nl] * acc[mt][nt][0];
            float v01 = c0s[nl + 1] * acc[mt][nt][1];
            float v10 = c0s[nl] * acc[mt][nt][2];
            float v11 = c0s[nl + 1] * acc[mt][nt][3];
#pragma unroll
            for (int j = 0; j < 16; j++) {
                v00 += t0[j] * w0[j];
                v01 += t0[j] * w1[j];
                v10 += t1[j] * w0[j];
                v11 += t1[j] * w1[j];
            }
            *(float2*)(out + (size_t)r0 * NDIM + n0 + nl) = make_float2(v00, v01);
            *(float2*)(out + (size_t)(r0 + 8) * NDIM + n0 + nl) = make_float2(v10, v11);
        }
    }
}

// ---------------- launch ----------------
extern "C" void kernel_launch(void* const* d_in, const int* in_sizes, int n_in,
                              void* d_out, int out_size) {
    const float* x   = (const float*)d_in[0];
    const float* U   = (const float*)d_in[1];
    const float* V   = (const float*)d_in[2];
    const float* S   = (const float*)d_in[3];
    const float* O   = (const float*)d_in[4];
    const float* mag = (const float*)d_in[5];
    const float* W   = (const float*)d_in[6];
    float* out = (float*)d_out;

    float *xr, *wr, *t, *bv, *bsq, *gram, *c0, *W2;
    cudaGetSymbolAddress((void**)&xr, g_xr);
    cudaGetSymbolAddress((void**)&wr, g_wr);
    cudaGetSymbolAddress((void**)&t, g_t);
    cudaGetSymbolAddress((void**)&bv, g_bv);
    cudaGetSymbolAddress((void**)&bsq, g_bsq);
    cudaGetSymbolAddress((void**)&gram, g_gram);
    cudaGetSymbolAddress((void**)&c0, g_c0);
    cudaGetSymbolAddress((void**)&W2, g_W2);

    cudaFuncSetAttribute(k_gemm, cudaFuncAttributeMaxDynamicSharedMemorySize, SMEM_TOTAL);

    k_xprep<<<MDIM / 32, 256>>>(x, V, xr, t);
    k_wprep<<<128 + 256, 256>>>(W, V, wr, bv, bsq, gram);
    k_comb<<<NDIM / 256, 256>>>(U, S, O, mag, bv, bsq, gram, c0, W2);
    k_gemm<<<(MDIM / BM) * (NDIM / BN), 256, SMEM_TOTAL>>>(xr, wr, t, c0, W2, out);
}